// round 10
// baseline (speedup 1.0000x reference)
#include <cuda_runtime.h>
#include <math.h>

// Shapes (fixed by the problem)
#define B_  4
#define H_  1024
#define W_  1024
#define F_  200000
#define V_  100000
#define HW_ (H_ * W_)

// Output element offsets (f32), in reference tuple order:
// uv_map(B,H,W,2) alpha(B,H,W) fim(B,H,W) wmap(B,H,W,3,1) faces_v_idx(B,F,3)
// normal_map(B,H,W,3) normal_map_cam(B,H,W,3) faces_v(B,F,3,3) faces_vt(1,F,3,2)
// position_map(B,H,W,3) position_map_cam(B,H,W,3) depth(B,H,W,1) v_uvz(B,V,3) v_front_mask(1,V)
#define O_UV       ((size_t)0)
#define O_ALPHA    ((size_t)8388608)
#define O_FIM      ((size_t)12582912)
#define O_WMAP     ((size_t)16777216)
#define O_FVIDX    ((size_t)29360128)
#define O_NORMAL   ((size_t)31760128)
#define O_NORMCAM  ((size_t)44343040)
#define O_FV       ((size_t)56925952)
#define O_FVT      ((size_t)64125952)
#define O_POS      ((size_t)65325952)
#define O_POSCAM   ((size_t)77908864)
#define O_DEPTH    ((size_t)90491776)
#define O_VUVZ     ((size_t)94686080)
#define O_MASK     ((size_t)95886080)

// Scratch (alloc-free rule: __device__ globals). ~17 MB.
__device__ float g_zinv[B_ * F_ * 3];   // 1/faces_v_uvz[...,2], (B,F,3)
__device__ float g_vn[F_ * 9];          // gathered face vertex normals (F,3,3)
__device__ float g_span;                // mesh_span

// ---------------------------------------------------------------------------
// 1) mesh_span = max over axes of (max - min) over vertices[0] (V,3)
// ---------------------------------------------------------------------------
__global__ void span_kernel(const float* __restrict__ verts) {
    __shared__ float s[6][1024];
    int t = threadIdx.x;
    float mn0 = INFINITY, mn1 = INFINITY, mn2 = INFINITY;
    float mx0 = -INFINITY, mx1 = -INFINITY, mx2 = -INFINITY;
    for (int i = t; i < V_; i += 1024) {
        float a = verts[i * 3 + 0];
        float b = verts[i * 3 + 1];
        float c = verts[i * 3 + 2];
        mn0 = fminf(mn0, a); mx0 = fmaxf(mx0, a);
        mn1 = fminf(mn1, b); mx1 = fmaxf(mx1, b);
        mn2 = fminf(mn2, c); mx2 = fmaxf(mx2, c);
    }
    s[0][t] = mn0; s[1][t] = mn1; s[2][t] = mn2;
    s[3][t] = mx0; s[4][t] = mx1; s[5][t] = mx2;
    __syncthreads();
    for (int off = 512; off > 0; off >>= 1) {
        if (t < off) {
            s[0][t] = fminf(s[0][t], s[0][t + off]);
            s[1][t] = fminf(s[1][t], s[1][t + off]);
            s[2][t] = fminf(s[2][t], s[2][t + off]);
            s[3][t] = fmaxf(s[3][t], s[3][t + off]);
            s[4][t] = fmaxf(s[4][t], s[4][t + off]);
            s[5][t] = fmaxf(s[5][t], s[5][t + off]);
        }
        __syncthreads();
    }
    if (t == 0) {
        g_span = fmaxf(fmaxf(s[3][0] - s[0][0], s[4][0] - s[1][0]),
                       s[5][0] - s[2][0]);
    }
}

// ---------------------------------------------------------------------------
// 2) Per-vertex: v_uvz transform (all batches) + v_front_mask (batch 0 only)
// ---------------------------------------------------------------------------
__global__ void vertex_kernel(const float* __restrict__ v_uvz,
                              const float* __restrict__ depth,
                              float* __restrict__ out) {
    int i = blockIdx.x * blockDim.x + threadIdx.x;
    if (i >= B_ * V_) return;
    float x = v_uvz[i * 3 + 0];
    float y = v_uvz[i * 3 + 1];
    float z = v_uvz[i * 3 + 2];
    float u = (x * 0.5f + 0.5f) * (float)W_;
    float v = (1.0f - (y * 0.5f + 0.5f)) * (float)H_;
    out[O_VUVZ + (size_t)i * 3 + 0] = u;
    out[O_VUVZ + (size_t)i * 3 + 1] = v;
    out[O_VUVZ + (size_t)i * 3 + 2] = z;

    if (i < V_) {  // batch 0: bilinear sample of depth[0], front mask
        float x0f = floorf(u);
        float y0f = floorf(v);
        float tx = u - x0f;
        float ty = v - y0f;
        int ix0 = min(max((int)x0f, 0), W_ - 1);
        int ix1 = min(ix0 + 1, W_ - 1);
        int iy0 = min(max((int)y0f, 0), H_ - 1);
        int iy1 = min(iy0 + 1, H_ - 1);
        float v00 = depth[iy0 * W_ + ix0];
        float v01 = depth[iy0 * W_ + ix1];
        float v10 = depth[iy1 * W_ + ix0];
        float v11 = depth[iy1 * W_ + ix1];
        float vd = v00 * (1.0f - tx) * (1.0f - ty)
                 + v01 * tx * (1.0f - ty)
                 + v10 * (1.0f - tx) * ty
                 + v11 * tx * ty;
        out[O_MASK + i] = (z - vd < g_span * 0.005f) ? 1.0f : 0.0f;
    }
}

// ---------------------------------------------------------------------------
// 3) Per-face-corner (F*3 threads): pre-gather vt/vn/v tables, 1/z, idx copy
// ---------------------------------------------------------------------------
__global__ void face_kernel(const float* __restrict__ verts,
                            const float* __restrict__ texc,
                            const float* __restrict__ norms,
                            const float* __restrict__ fvuvz,
                            const int*   __restrict__ vt_idx,
                            const int*   __restrict__ vn_idx,
                            const int*   __restrict__ v_idx,
                            float* __restrict__ out) {
    int t = blockIdx.x * blockDim.x + threadIdx.x;  // t = f*3 + k
    if (t >= F_ * 3) return;

    int vt = vt_idx[t];
    out[O_FVT + (size_t)t * 2 + 0] = texc[(size_t)vt * 2 + 0];
    out[O_FVT + (size_t)t * 2 + 1] = texc[(size_t)vt * 2 + 1];

    int vn = vn_idx[t];
    g_vn[(size_t)t * 3 + 0] = norms[(size_t)vn * 3 + 0];
    g_vn[(size_t)t * 3 + 1] = norms[(size_t)vn * 3 + 1];
    g_vn[(size_t)t * 3 + 2] = norms[(size_t)vn * 3 + 2];

#pragma unroll
    for (int b = 0; b < B_; b++) {
        int vi = v_idx[(size_t)b * F_ * 3 + t];
        out[O_FVIDX + (size_t)b * F_ * 3 + t] = (float)vi;
        size_t ob = O_FV + (size_t)b * F_ * 9 + (size_t)t * 3;
        out[ob + 0] = verts[(size_t)vi * 3 + 0];
        out[ob + 1] = verts[(size_t)vi * 3 + 1];
        out[ob + 2] = verts[(size_t)vi * 3 + 2];
        g_zinv[(size_t)b * F_ * 3 + t] =
            1.0f / fvuvz[(size_t)b * F_ * 9 + (size_t)t * 3 + 2];
    }
}

// ---------------------------------------------------------------------------
// 4) Per-pixel (B*H*W threads): everything else
// ---------------------------------------------------------------------------
__global__ void __launch_bounds__(256)
pixel_kernel(const int*   __restrict__ fim,
             const float* __restrict__ depth,
             const float* __restrict__ alpha,
             const float* __restrict__ wm,
             const float* __restrict__ pose,
             float* __restrict__ out) {
    int p = blockIdx.x * blockDim.x + threadIdx.x;
    if (p >= B_ * HW_) return;
    int b = p >> 20;  // HW_ = 2^20

    int f = fim[p];
    float d = depth[p];
    out[O_ALPHA + p] = alpha[p];
    out[O_FIM + p]   = (float)f;
    out[O_DEPTH + p] = d;

    // wmap = (1/z) * weight * depth
    size_t zb = (size_t)b * F_ * 3 + (size_t)f * 3;
    float w0 = g_zinv[zb + 0] * wm[(size_t)p * 3 + 0] * d;
    float w1 = g_zinv[zb + 1] * wm[(size_t)p * 3 + 1] * d;
    float w2 = g_zinv[zb + 2] * wm[(size_t)p * 3 + 2] * d;
    out[O_WMAP + (size_t)p * 3 + 0] = w0;
    out[O_WMAP + (size_t)p * 3 + 1] = w1;
    out[O_WMAP + (size_t)p * 3 + 2] = w2;

    // uv_map: gather pre-gathered faces_vt (6 contiguous floats), frac
    {
        const float* vt = out + O_FVT + (size_t)f * 6;
        float u = w0 * vt[0] + w1 * vt[2] + w2 * vt[4];
        float v = w0 * vt[1] + w1 * vt[3] + w2 * vt[5];
        out[O_UV + (size_t)p * 2 + 0] = u - floorf(u);
        out[O_UV + (size_t)p * 2 + 1] = v - floorf(v);
    }

    // pose row (R | t) for this batch
    const float* P = pose + b * 12;

    // normal_map + normal_map_cam
    {
        const float* vn = g_vn + (size_t)f * 9;
        float nx = w0 * vn[0] + w1 * vn[3] + w2 * vn[6];
        float ny = w0 * vn[1] + w1 * vn[4] + w2 * vn[7];
        float nz = w0 * vn[2] + w1 * vn[5] + w2 * vn[8];
        float inv = 1.0f / fmaxf(sqrtf(nx * nx + ny * ny + nz * nz), 1e-12f);
        nx *= inv; ny *= inv; nz *= inv;
        out[O_NORMAL + (size_t)p * 3 + 0] = nx;
        out[O_NORMAL + (size_t)p * 3 + 1] = ny;
        out[O_NORMAL + (size_t)p * 3 + 2] = nz;

        float cx = P[0] * nx + P[1] * ny + P[2]  * nz;
        float cy = P[4] * nx + P[5] * ny + P[6]  * nz;
        float cz = P[8] * nx + P[9] * ny + P[10] * nz;
        float ci = 1.0f / fmaxf(sqrtf(cx * cx + cy * cy + cz * cz), 1e-12f);
        out[O_NORMCAM + (size_t)p * 3 + 0] = cx * ci;
        out[O_NORMCAM + (size_t)p * 3 + 1] = cy * ci;
        out[O_NORMCAM + (size_t)p * 3 + 2] = cz * ci;
    }

    // position_map + position_map_cam — NOTE: reference uses faces_v[0][fim]
    // (batch-0 face vertices) for ALL batches.
    {
        const float* fv = out + O_FV + (size_t)f * 9;
        float px = w0 * fv[0] + w1 * fv[3] + w2 * fv[6];
        float py = w0 * fv[1] + w1 * fv[4] + w2 * fv[7];
        float pz = w0 * fv[2] + w1 * fv[5] + w2 * fv[8];
        out[O_POS + (size_t)p * 3 + 0] = px;
        out[O_POS + (size_t)p * 3 + 1] = py;
        out[O_POS + (size_t)p * 3 + 2] = pz;

        out[O_POSCAM + (size_t)p * 3 + 0] = P[0] * px + P[1] * py + P[2]  * pz + P[3];
        out[O_POSCAM + (size_t)p * 3 + 1] = P[4] * px + P[5] * py + P[6]  * pz + P[7];
        out[O_POSCAM + (size_t)p * 3 + 2] = P[8] * px + P[9] * py + P[10] * pz + P[11];
    }
}

// ---------------------------------------------------------------------------
// Launch. Input order per setup_inputs:
// 0 vertices 1 vertices_texcoords 2 vertices_normals 3 pose 4 depth 5 alpha
// 6 weight_map 7 v_uvz 8 faces_v_uvz 9 face_index_map 10 faces_vt_idx
// 11 faces_vn_idx 12 faces_v_idx
// ---------------------------------------------------------------------------
extern "C" void kernel_launch(void* const* d_in, const int* in_sizes, int n_in,
                              void* d_out, int out_size) {
    const float* vertices = (const float*)d_in[0];
    const float* texc     = (const float*)d_in[1];
    const float* norms    = (const float*)d_in[2];
    const float* pose     = (const float*)d_in[3];
    const float* depth    = (const float*)d_in[4];
    const float* alpha    = (const float*)d_in[5];
    const float* wm       = (const float*)d_in[6];
    const float* v_uvz    = (const float*)d_in[7];
    const float* fvuvz    = (const float*)d_in[8];
    const int*   fim      = (const int*)d_in[9];
    const int*   vt_idx   = (const int*)d_in[10];
    const int*   vn_idx   = (const int*)d_in[11];
    const int*   v_idx    = (const int*)d_in[12];
    float* out = (float*)d_out;

    span_kernel<<<1, 1024>>>(vertices);

    {
        int n = B_ * V_;
        vertex_kernel<<<(n + 255) / 256, 256>>>(v_uvz, depth, out);
    }
    {
        int n = F_ * 3;
        face_kernel<<<(n + 255) / 256, 256>>>(vertices, texc, norms, fvuvz,
                                              vt_idx, vn_idx, v_idx, out);
    }
    {
        int n = B_ * HW_;
        pixel_kernel<<<(n + 255) / 256, 256>>>(fim, depth, alpha, wm, pose, out);
    }
}

// round 11
// speedup vs baseline: 1.0046x; 1.0046x over previous
#include <cuda_runtime.h>
#include <math.h>

// Shapes (fixed by the problem)
#define B_  4
#define H_  1024
#define W_  1024
#define F_  200000
#define V_  100000
#define HW_ (H_ * W_)

// Output element offsets (f32), in reference tuple order:
// uv_map(B,H,W,2) alpha(B,H,W) fim(B,H,W) wmap(B,H,W,3,1) faces_v_idx(B,F,3)
// normal_map(B,H,W,3) normal_map_cam(B,H,W,3) faces_v(B,F,3,3) faces_vt(1,F,3,2)
// position_map(B,H,W,3) position_map_cam(B,H,W,3) depth(B,H,W,1) v_uvz(B,V,3) v_front_mask(1,V)
#define O_UV       ((size_t)0)
#define O_ALPHA    ((size_t)8388608)
#define O_FIM      ((size_t)12582912)
#define O_WMAP     ((size_t)16777216)
#define O_FVIDX    ((size_t)29360128)
#define O_NORMAL   ((size_t)31760128)
#define O_NORMCAM  ((size_t)44343040)
#define O_FV       ((size_t)56925952)
#define O_FVT      ((size_t)64125952)
#define O_POS      ((size_t)65325952)
#define O_POSCAM   ((size_t)77908864)
#define O_DEPTH    ((size_t)90491776)
#define O_VUVZ     ((size_t)94686080)
#define O_MASK     ((size_t)95886080)

// Scratch (alloc-free rule: __device__ globals). ~17 MB.
__device__ float g_zinv[B_ * F_ * 3];   // 1/faces_v_uvz[...,2], (B,F,3)
__device__ float g_vn[F_ * 9];          // gathered face vertex normals (F,3,3)
__device__ float g_span;                // mesh_span

// ---------------------------------------------------------------------------
// 1) mesh_span = max over axes of (max - min) over vertices[0] (V,3)
// ---------------------------------------------------------------------------
__global__ void span_kernel(const float* __restrict__ verts) {
    __shared__ float s[6][1024];
    int t = threadIdx.x;
    float mn0 = INFINITY, mn1 = INFINITY, mn2 = INFINITY;
    float mx0 = -INFINITY, mx1 = -INFINITY, mx2 = -INFINITY;
    for (int i = t; i < V_; i += 1024) {
        float a = verts[i * 3 + 0];
        float b = verts[i * 3 + 1];
        float c = verts[i * 3 + 2];
        mn0 = fminf(mn0, a); mx0 = fmaxf(mx0, a);
        mn1 = fminf(mn1, b); mx1 = fmaxf(mx1, b);
        mn2 = fminf(mn2, c); mx2 = fmaxf(mx2, c);
    }
    s[0][t] = mn0; s[1][t] = mn1; s[2][t] = mn2;
    s[3][t] = mx0; s[4][t] = mx1; s[5][t] = mx2;
    __syncthreads();
    for (int off = 512; off > 0; off >>= 1) {
        if (t < off) {
            s[0][t] = fminf(s[0][t], s[0][t + off]);
            s[1][t] = fminf(s[1][t], s[1][t + off]);
            s[2][t] = fminf(s[2][t], s[2][t + off]);
            s[3][t] = fmaxf(s[3][t], s[3][t + off]);
            s[4][t] = fmaxf(s[4][t], s[4][t + off]);
            s[5][t] = fmaxf(s[5][t], s[5][t + off]);
        }
        __syncthreads();
    }
    if (t == 0) {
        g_span = fmaxf(fmaxf(s[3][0] - s[0][0], s[4][0] - s[1][0]),
                       s[5][0] - s[2][0]);
    }
}

// ---------------------------------------------------------------------------
// 2) Per-vertex: v_uvz transform (all batches) + v_front_mask (batch 0 only)
// ---------------------------------------------------------------------------
__global__ void vertex_kernel(const float* __restrict__ v_uvz,
                              const float* __restrict__ depth,
                              float* __restrict__ out) {
    int i = blockIdx.x * blockDim.x + threadIdx.x;
    if (i >= B_ * V_) return;
    float x = v_uvz[i * 3 + 0];
    float y = v_uvz[i * 3 + 1];
    float z = v_uvz[i * 3 + 2];
    float u = (x * 0.5f + 0.5f) * (float)W_;
    float v = (1.0f - (y * 0.5f + 0.5f)) * (float)H_;
    out[O_VUVZ + (size_t)i * 3 + 0] = u;
    out[O_VUVZ + (size_t)i * 3 + 1] = v;
    out[O_VUVZ + (size_t)i * 3 + 2] = z;

    if (i < V_) {  // batch 0: bilinear sample of depth[0], front mask
        float x0f = floorf(u);
        float y0f = floorf(v);
        float tx = u - x0f;
        float ty = v - y0f;
        int ix0 = min(max((int)x0f, 0), W_ - 1);
        int ix1 = min(ix0 + 1, W_ - 1);
        int iy0 = min(max((int)y0f, 0), H_ - 1);
        int iy1 = min(iy0 + 1, H_ - 1);
        float v00 = depth[iy0 * W_ + ix0];
        float v01 = depth[iy0 * W_ + ix1];
        float v10 = depth[iy1 * W_ + ix0];
        float v11 = depth[iy1 * W_ + ix1];
        float vd = v00 * (1.0f - tx) * (1.0f - ty)
                 + v01 * tx * (1.0f - ty)
                 + v10 * (1.0f - tx) * ty
                 + v11 * tx * ty;
        out[O_MASK + i] = (z - vd < g_span * 0.005f) ? 1.0f : 0.0f;
    }
}

// ---------------------------------------------------------------------------
// 3) Per-face-corner (F*3 threads): pre-gather vt/vn/v tables, 1/z, idx copy
// ---------------------------------------------------------------------------
__global__ void face_kernel(const float* __restrict__ verts,
                            const float* __restrict__ texc,
                            const float* __restrict__ norms,
                            const float* __restrict__ fvuvz,
                            const int*   __restrict__ vt_idx,
                            const int*   __restrict__ vn_idx,
                            const int*   __restrict__ v_idx,
                            float* __restrict__ out) {
    int t = blockIdx.x * blockDim.x + threadIdx.x;  // t = f*3 + k
    if (t >= F_ * 3) return;

    int vt = vt_idx[t];
    out[O_FVT + (size_t)t * 2 + 0] = texc[(size_t)vt * 2 + 0];
    out[O_FVT + (size_t)t * 2 + 1] = texc[(size_t)vt * 2 + 1];

    int vn = vn_idx[t];
    g_vn[(size_t)t * 3 + 0] = norms[(size_t)vn * 3 + 0];
    g_vn[(size_t)t * 3 + 1] = norms[(size_t)vn * 3 + 1];
    g_vn[(size_t)t * 3 + 2] = norms[(size_t)vn * 3 + 2];

#pragma unroll
    for (int b = 0; b < B_; b++) {
        int vi = v_idx[(size_t)b * F_ * 3 + t];
        out[O_FVIDX + (size_t)b * F_ * 3 + t] = (float)vi;
        size_t ob = O_FV + (size_t)b * F_ * 9 + (size_t)t * 3;
        out[ob + 0] = verts[(size_t)vi * 3 + 0];
        out[ob + 1] = verts[(size_t)vi * 3 + 1];
        out[ob + 2] = verts[(size_t)vi * 3 + 2];
        g_zinv[(size_t)b * F_ * 3 + t] =
            1.0f / fvuvz[(size_t)b * F_ * 9 + (size_t)t * 3 + 2];
    }
}

// ---------------------------------------------------------------------------
// 4) Per-pixel (B*H*W threads): everything else
// ---------------------------------------------------------------------------
__global__ void __launch_bounds__(256)
pixel_kernel(const int*   __restrict__ fim,
             const float* __restrict__ depth,
             const float* __restrict__ alpha,
             const float* __restrict__ wm,
             const float* __restrict__ pose,
             float* __restrict__ out) {
    int p = blockIdx.x * blockDim.x + threadIdx.x;
    if (p >= B_ * HW_) return;
    int b = p >> 20;  // HW_ = 2^20

    int f = fim[p];
    float d = depth[p];
    out[O_ALPHA + p] = alpha[p];
    out[O_FIM + p]   = (float)f;
    out[O_DEPTH + p] = d;

    // wmap = (1/z) * weight * depth
    size_t zb = (size_t)b * F_ * 3 + (size_t)f * 3;
    float w0 = g_zinv[zb + 0] * wm[(size_t)p * 3 + 0] * d;
    float w1 = g_zinv[zb + 1] * wm[(size_t)p * 3 + 1] * d;
    float w2 = g_zinv[zb + 2] * wm[(size_t)p * 3 + 2] * d;
    out[O_WMAP + (size_t)p * 3 + 0] = w0;
    out[O_WMAP + (size_t)p * 3 + 1] = w1;
    out[O_WMAP + (size_t)p * 3 + 2] = w2;

    // uv_map: gather pre-gathered faces_vt (6 contiguous floats), frac
    {
        const float* vt = out + O_FVT + (size_t)f * 6;
        float u = w0 * vt[0] + w1 * vt[2] + w2 * vt[4];
        float v = w0 * vt[1] + w1 * vt[3] + w2 * vt[5];
        out[O_UV + (size_t)p * 2 + 0] = u - floorf(u);
        out[O_UV + (size_t)p * 2 + 1] = v - floorf(v);
    }

    // pose row (R | t) for this batch
    const float* P = pose + b * 12;

    // normal_map + normal_map_cam
    {
        const float* vn = g_vn + (size_t)f * 9;
        float nx = w0 * vn[0] + w1 * vn[3] + w2 * vn[6];
        float ny = w0 * vn[1] + w1 * vn[4] + w2 * vn[7];
        float nz = w0 * vn[2] + w1 * vn[5] + w2 * vn[8];
        float inv = 1.0f / fmaxf(sqrtf(nx * nx + ny * ny + nz * nz), 1e-12f);
        nx *= inv; ny *= inv; nz *= inv;
        out[O_NORMAL + (size_t)p * 3 + 0] = nx;
        out[O_NORMAL + (size_t)p * 3 + 1] = ny;
        out[O_NORMAL + (size_t)p * 3 + 2] = nz;

        float cx = P[0] * nx + P[1] * ny + P[2]  * nz;
        float cy = P[4] * nx + P[5] * ny + P[6]  * nz;
        float cz = P[8] * nx + P[9] * ny + P[10] * nz;
        float ci = 1.0f / fmaxf(sqrtf(cx * cx + cy * cy + cz * cz), 1e-12f);
        out[O_NORMCAM + (size_t)p * 3 + 0] = cx * ci;
        out[O_NORMCAM + (size_t)p * 3 + 1] = cy * ci;
        out[O_NORMCAM + (size_t)p * 3 + 2] = cz * ci;
    }

    // position_map + position_map_cam — NOTE: reference uses faces_v[0][fim]
    // (batch-0 face vertices) for ALL batches.
    {
        const float* fv = out + O_FV + (size_t)f * 9;
        float px = w0 * fv[0] + w1 * fv[3] + w2 * fv[6];
        float py = w0 * fv[1] + w1 * fv[4] + w2 * fv[7];
        float pz = w0 * fv[2] + w1 * fv[5] + w2 * fv[8];
        out[O_POS + (size_t)p * 3 + 0] = px;
        out[O_POS + (size_t)p * 3 + 1] = py;
        out[O_POS + (size_t)p * 3 + 2] = pz;

        out[O_POSCAM + (size_t)p * 3 + 0] = P[0] * px + P[1] * py + P[2]  * pz + P[3];
        out[O_POSCAM + (size_t)p * 3 + 1] = P[4] * px + P[5] * py + P[6]  * pz + P[7];
        out[O_POSCAM + (size_t)p * 3 + 2] = P[8] * px + P[9] * py + P[10] * pz + P[11];
    }
}

// ---------------------------------------------------------------------------
// Launch. Input order per setup_inputs:
// 0 vertices 1 vertices_texcoords 2 vertices_normals 3 pose 4 depth 5 alpha
// 6 weight_map 7 v_uvz 8 faces_v_uvz 9 face_index_map 10 faces_vt_idx
// 11 faces_vn_idx 12 faces_v_idx
// ---------------------------------------------------------------------------
extern "C" void kernel_launch(void* const* d_in, const int* in_sizes, int n_in,
                              void* d_out, int out_size) {
    const float* vertices = (const float*)d_in[0];
    const float* texc     = (const float*)d_in[1];
    const float* norms    = (const float*)d_in[2];
    const float* pose     = (const float*)d_in[3];
    const float* depth    = (const float*)d_in[4];
    const float* alpha    = (const float*)d_in[5];
    const float* wm       = (const float*)d_in[6];
    const float* v_uvz    = (const float*)d_in[7];
    const float* fvuvz    = (const float*)d_in[8];
    const int*   fim      = (const int*)d_in[9];
    const int*   vt_idx   = (const int*)d_in[10];
    const int*   vn_idx   = (const int*)d_in[11];
    const int*   v_idx    = (const int*)d_in[12];
    float* out = (float*)d_out;

    span_kernel<<<1, 1024>>>(vertices);

    {
        int n = B_ * V_;
        vertex_kernel<<<(n + 255) / 256, 256>>>(v_uvz, depth, out);
    }
    {
        int n = F_ * 3;
        face_kernel<<<(n + 255) / 256, 256>>>(vertices, texc, norms, fvuvz,
                                              vt_idx, vn_idx, v_idx, out);
    }
    {
        int n = B_ * HW_;
        pixel_kernel<<<(n + 255) / 256, 256>>>(fim, depth, alpha, wm, pose, out);
    }
}